// round 3
// baseline (speedup 1.0000x reference)
#include <cuda_runtime.h>
#include <cstdint>

// Problem constants
#define NREL 16
#define D 128
#define NNODES 524288

#define BM 128
#define XSTRIDE 132                 // smem row stride in floats (pad: bank = laneid, conflict-free)
#define TILES (NNODES / BM)         // 4096
#define GRID 592                    // ~4 waves on 148 SMs, grid-stride over tiles

// Pre-permuted W_eff in m16n8k8 tf32 B-fragment layout:
// index ((ki*16 + nf)*32 + lane) -> float2 {b0, b1}
//   b0 = W[ki*8 + lane%4    ][nf*8 + lane/4]
//   b1 = W[ki*8 + lane%4 + 4][nf*8 + lane/4]
__device__ float2 g_wfrag[16 * 16 * 32];

__device__ __forceinline__ uint32_t f2tf32(float f) {
    uint32_t r;
    asm("cvt.rna.tf32.f32 %0, %1;" : "=r"(r) : "f"(f));
    return r;
}

__device__ __forceinline__ void cp_async16(void* dst_smem, const void* src) {
    uint32_t d = (uint32_t)__cvta_generic_to_shared(dst_smem);
    asm volatile("cp.async.cg.shared.global [%0], [%1], 16;" :: "r"(d), "l"(src));
}
__device__ __forceinline__ void cp_commit() {
    asm volatile("cp.async.commit_group;");
}
template <int N>
__device__ __forceinline__ void cp_wait() {
    asm volatile("cp.async.wait_group %0;" :: "n"(N));
}

__device__ __forceinline__ void mma_tf32(float* c, const uint32_t* a, uint32_t b0, uint32_t b1) {
    asm volatile(
        "mma.sync.aligned.m16n8k8.row.col.f32.tf32.tf32.f32 "
        "{%0,%1,%2,%3}, {%4,%5,%6,%7}, {%8,%9}, {%0,%1,%2,%3};\n"
        : "+f"(c[0]), "+f"(c[1]), "+f"(c[2]), "+f"(c[3])
        : "r"(a[0]), "r"(a[1]), "r"(a[2]), "r"(a[3]), "r"(b0), "r"(b1));
}

// ---------------------------------------------------------------------------
// Kernel 1: fold 16 relations into W_eff, tf32-round, store in fragment layout
// ---------------------------------------------------------------------------
__global__ void prep_kernel(const float* __restrict__ W, const float* __restrict__ s) {
    int idx  = blockIdx.x * 256 + threadIdx.x;   // 0..8191
    int lane = idx & 31;
    int nf   = (idx >> 5) & 15;
    int ki   = idx >> 9;

    int k0 = ki * 8 + (lane & 3);
    int n  = nf * 8 + (lane >> 2);

    float b0 = 0.f, b1 = 0.f;
#pragma unroll
    for (int r = 0; r < NREL; r++) {
        float sc = s[r];
        b0 = fmaf(sc, W[(r * D + k0) * D + n], b0);
        b1 = fmaf(sc, W[(r * D + k0 + 4) * D + n], b1);
    }
    float2 v;
    v.x = __uint_as_float(f2tf32(b0));
    v.y = __uint_as_float(f2tf32(b1));
    g_wfrag[idx] = v;
}

// ---------------------------------------------------------------------------
// Kernel 2: grid-stride tiled GEMM. DB = 1 -> double-buffered X (prefetch
// next tile during MMA); DB = 0 -> single buffer (fallback, lower smem).
// ---------------------------------------------------------------------------
__device__ __forceinline__ void load_x_tile(const float* __restrict__ gx,
                                            float* __restrict__ dst, int tid) {
    // 128 rows * 128 floats = 4096 x 16B chunks; 256 threads x 16 chunks, coalesced
#pragma unroll
    for (int i = 0; i < 16; i++) {
        int c   = tid + i * 256;
        int row = c >> 5;
        int cc  = c & 31;
        cp_async16(dst + row * XSTRIDE + cc * 4, gx + row * D + cc * 4);
    }
    cp_commit();
}

template <int DB>
__global__ void __launch_bounds__(256, 1)
gemm_kernel(const float* __restrict__ X, float* __restrict__ Y) {
    extern __shared__ float smem[];
    float2* sw = (float2*)smem;          // 8192 float2 = 64 KB W fragments
    float*  sx = smem + 16384;           // (1+DB) x [128][132] X buffers

    const int tid  = threadIdx.x;
    const int warp = tid >> 5;
    const int lane = tid & 31;
    const int wm   = warp >> 1;          // 0..3  (M groups of 32 rows)
    const int wn   = warp & 1;           // 0..1  (N groups of 64 cols)

    // Stage W fragments into smem (cp.async group 0)
    {
        const float* gw = (const float*)g_wfrag;
#pragma unroll
        for (int i = 0; i < 16; i++) {
            int c = tid + i * 256;       // 16B chunk 0..4095
            cp_async16(&smem[c * 4], gw + c * 4);
        }
    }
    cp_commit();

    int tile = blockIdx.x;
    load_x_tile(X + (size_t)tile * BM * D, sx, tid);   // group 1

    int buf = 0;
    for (; tile < TILES; tile += GRID) {
        int next = tile + GRID;
        if (DB && next < TILES) {
            load_x_tile(X + (size_t)next * BM * D, sx + (buf ^ 1) * (BM * XSTRIDE), tid);
            cp_wait<1>();                // current tile (and W) landed
        } else {
            cp_wait<0>();
        }
        __syncthreads();

        const float* xb = sx + buf * (BM * XSTRIDE);

        float acc[2][8][4];
#pragma unroll
        for (int mf = 0; mf < 2; mf++)
#pragma unroll
            for (int nf = 0; nf < 8; nf++)
#pragma unroll
                for (int q = 0; q < 4; q++) acc[mf][nf][q] = 0.f;

#pragma unroll
        for (int ki = 0; ki < 16; ki++) {
            // A fragments (bank pattern with XSTRIDE=132 -> bank == laneid, conflict-free)
            uint32_t a[2][4];
#pragma unroll
            for (int mf = 0; mf < 2; mf++) {
                const float* ap = xb + (wm * 32 + mf * 16 + (lane >> 2)) * XSTRIDE
                                     + ki * 8 + (lane & 3);
                a[mf][0] = f2tf32(ap[0]);
                a[mf][1] = f2tf32(ap[8 * XSTRIDE]);
                a[mf][2] = f2tf32(ap[4]);
                a[mf][3] = f2tf32(ap[8 * XSTRIDE + 4]);
            }
#pragma unroll
            for (int nf = 0; nf < 8; nf++) {
                float2 b = sw[(ki * 16 + wn * 8 + nf) * 32 + lane];  // LDS.64, conflict-free
                uint32_t b0 = __float_as_uint(b.x);
                uint32_t b1 = __float_as_uint(b.y);
#pragma unroll
                for (int mf = 0; mf < 2; mf++)
                    mma_tf32(acc[mf][nf], a[mf], b0, b1);
            }
        }

        // Store: STG.64, each covers full 32B sectors
        float* yp = Y + (size_t)tile * BM * D;
#pragma unroll
        for (int mf = 0; mf < 2; mf++) {
            int row0 = wm * 32 + mf * 16 + (lane >> 2);
#pragma unroll
            for (int nf = 0; nf < 8; nf++) {
                int col = wn * 64 + nf * 8 + 2 * (lane & 3);
                float2 v0 = make_float2(acc[mf][nf][0], acc[mf][nf][1]);
                float2 v1 = make_float2(acc[mf][nf][2], acc[mf][nf][3]);
                *(float2*)(yp + (size_t)row0 * D + col)       = v0;
                *(float2*)(yp + (size_t)(row0 + 8) * D + col) = v1;
            }
        }
        __syncthreads();   // protect buf from next iteration's prefetch
        if (DB) buf ^= 1;

        if (!DB && tile + GRID < TILES)
            load_x_tile(X + (size_t)(tile + GRID) * BM * D, sx, tid);
    }
}

// ---------------------------------------------------------------------------
extern "C" void kernel_launch(void* const* d_in, const int* in_sizes, int n_in,
                              void* d_out, int out_size) {
    const float* X = (const float*)d_in[0];  // [524288, 128]
    const float* W = (const float*)d_in[1];  // [16, 128, 128]
    const float* s = (const float*)d_in[2];  // [16, 1]
    float* Y = (float*)d_out;                // [524288, 128]

    prep_kernel<<<32, 256>>>(W, s);

    size_t smem_db = (16384 + 2 * BM * XSTRIDE) * sizeof(float);  // ~196 KB
    size_t smem_sb = (16384 + 1 * BM * XSTRIDE) * sizeof(float);  // ~132 KB

    cudaError_t e = cudaFuncSetAttribute(
        gemm_kernel<1>, cudaFuncAttributeMaxDynamicSharedMemorySize, (int)smem_db);
    if (e == cudaSuccess) {
        gemm_kernel<1><<<GRID, 256, smem_db>>>(X, Y);
    } else {
        cudaGetLastError();  // clear sticky error
        cudaFuncSetAttribute(gemm_kernel<0>,
                             cudaFuncAttributeMaxDynamicSharedMemorySize, (int)smem_sb);
        gemm_kernel<0><<<GRID, 256, smem_sb>>>(X, Y);
    }
}

// round 5
// speedup vs baseline: 1.0064x; 1.0064x over previous
#include <cuda_runtime.h>
#include <cstdint>

// Problem constants
#define NREL 16
#define D 128
#define NNODES 524288

#define BM 128
#define XSTRIDE 132                 // smem row stride in floats (pad: bank = laneid, conflict-free)
#define TILES (NNODES / BM)         // 4096
#define GRID 592                    // ~4 waves on 148 SMs, grid-stride over tiles

// Pre-permuted W_eff in m16n8k8 tf32 B-fragment layout:
// index ((ki*16 + nf)*32 + lane) -> float2 {b0, b1}
//   b0 = W[ki*8 + lane%4    ][nf*8 + lane/4]
//   b1 = W[ki*8 + lane%4 + 4][nf*8 + lane/4]
__device__ float2 g_wfrag[16 * 16 * 32];

__device__ __forceinline__ uint32_t f2tf32(float f) {
    uint32_t r;
    asm("cvt.rna.tf32.f32 %0, %1;" : "=r"(r) : "f"(f));
    return r;
}

__device__ __forceinline__ void cp_async16(void* dst_smem, const void* src) {
    uint32_t d = (uint32_t)__cvta_generic_to_shared(dst_smem);
    asm volatile("cp.async.cg.shared.global [%0], [%1], 16;" :: "r"(d), "l"(src));
}
__device__ __forceinline__ void cp_commit() {
    asm volatile("cp.async.commit_group;");
}
template <int N>
__device__ __forceinline__ void cp_wait() {
    asm volatile("cp.async.wait_group %0;" :: "n"(N));
}

__device__ __forceinline__ void mma_tf32(float* c, const uint32_t* a, uint32_t b0, uint32_t b1) {
    asm volatile(
        "mma.sync.aligned.m16n8k8.row.col.f32.tf32.tf32.f32 "
        "{%0,%1,%2,%3}, {%4,%5,%6,%7}, {%8,%9}, {%0,%1,%2,%3};\n"
        : "+f"(c[0]), "+f"(c[1]), "+f"(c[2]), "+f"(c[3])
        : "r"(a[0]), "r"(a[1]), "r"(a[2]), "r"(a[3]), "r"(b0), "r"(b1));
}

// ---------------------------------------------------------------------------
// Kernel 1: fold 16 relations into W_eff, tf32-round, store in fragment layout
// ---------------------------------------------------------------------------
__global__ void prep_kernel(const float* __restrict__ W, const float* __restrict__ s) {
    int idx  = blockIdx.x * 256 + threadIdx.x;   // 0..8191
    int lane = idx & 31;
    int nf   = (idx >> 5) & 15;
    int ki   = idx >> 9;

    int k0 = ki * 8 + (lane & 3);
    int n  = nf * 8 + (lane >> 2);

    float b0 = 0.f, b1 = 0.f;
#pragma unroll
    for (int r = 0; r < NREL; r++) {
        float sc = s[r];
        b0 = fmaf(sc, W[(r * D + k0) * D + n], b0);
        b1 = fmaf(sc, W[(r * D + k0 + 4) * D + n], b1);
    }
    float2 v;
    v.x = __uint_as_float(f2tf32(b0));
    v.y = __uint_as_float(f2tf32(b1));
    g_wfrag[idx] = v;
}

// ---------------------------------------------------------------------------
// Kernel 2: grid-stride tiled GEMM. DB = 1 -> double-buffered X (prefetch
// next tile during MMA); DB = 0 -> single buffer (fallback, lower smem).
// ---------------------------------------------------------------------------
__device__ __forceinline__ void load_x_tile(const float* __restrict__ gx,
                                            float* __restrict__ dst, int tid) {
    // 128 rows * 128 floats = 4096 x 16B chunks; 256 threads x 16 chunks, coalesced
#pragma unroll
    for (int i = 0; i < 16; i++) {
        int c   = tid + i * 256;
        int row = c >> 5;
        int cc  = c & 31;
        cp_async16(dst + row * XSTRIDE + cc * 4, gx + row * D + cc * 4);
    }
    cp_commit();
}

template <int DB>
__global__ void __launch_bounds__(256, 1)
gemm_kernel(const float* __restrict__ X, float* __restrict__ Y) {
    extern __shared__ float smem[];
    float2* sw = (float2*)smem;          // 8192 float2 = 64 KB W fragments
    float*  sx = smem + 16384;           // (1+DB) x [128][132] X buffers

    const int tid  = threadIdx.x;
    const int warp = tid >> 5;
    const int lane = tid & 31;
    const int wm   = warp >> 1;          // 0..3  (M groups of 32 rows)
    const int wn   = warp & 1;           // 0..1  (N groups of 64 cols)

    // Stage W fragments into smem (cp.async group 0)
    {
        const float* gw = (const float*)g_wfrag;
#pragma unroll
        for (int i = 0; i < 16; i++) {
            int c = tid + i * 256;       // 16B chunk 0..4095
            cp_async16(&smem[c * 4], gw + c * 4);
        }
    }
    cp_commit();

    int tile = blockIdx.x;
    load_x_tile(X + (size_t)tile * BM * D, sx, tid);   // group 1

    int buf = 0;
    for (; tile < TILES; tile += GRID) {
        int next = tile + GRID;
        if (DB && next < TILES) {
            load_x_tile(X + (size_t)next * BM * D, sx + (buf ^ 1) * (BM * XSTRIDE), tid);
            cp_wait<1>();                // current tile (and W) landed
        } else {
            cp_wait<0>();
        }
        __syncthreads();

        const float* xb = sx + buf * (BM * XSTRIDE);

        float acc[2][8][4];
#pragma unroll
        for (int mf = 0; mf < 2; mf++)
#pragma unroll
            for (int nf = 0; nf < 8; nf++)
#pragma unroll
                for (int q = 0; q < 4; q++) acc[mf][nf][q] = 0.f;

#pragma unroll
        for (int ki = 0; ki < 16; ki++) {
            // A fragments (bank pattern with XSTRIDE=132 -> bank == laneid, conflict-free)
            uint32_t a[2][4];
#pragma unroll
            for (int mf = 0; mf < 2; mf++) {
                const float* ap = xb + (wm * 32 + mf * 16 + (lane >> 2)) * XSTRIDE
                                     + ki * 8 + (lane & 3);
                a[mf][0] = f2tf32(ap[0]);
                a[mf][1] = f2tf32(ap[8 * XSTRIDE]);
                a[mf][2] = f2tf32(ap[4]);
                a[mf][3] = f2tf32(ap[8 * XSTRIDE + 4]);
            }
#pragma unroll
            for (int nf = 0; nf < 8; nf++) {
                float2 b = sw[(ki * 16 + wn * 8 + nf) * 32 + lane];  // LDS.64, conflict-free
                uint32_t b0 = __float_as_uint(b.x);
                uint32_t b1 = __float_as_uint(b.y);
#pragma unroll
                for (int mf = 0; mf < 2; mf++)
                    mma_tf32(acc[mf][nf], a[mf], b0, b1);
            }
        }

        // Store: STG.64, each covers full 32B sectors
        float* yp = Y + (size_t)tile * BM * D;
#pragma unroll
        for (int mf = 0; mf < 2; mf++) {
            int row0 = wm * 32 + mf * 16 + (lane >> 2);
#pragma unroll
            for (int nf = 0; nf < 8; nf++) {
                int col = wn * 64 + nf * 8 + 2 * (lane & 3);
                float2 v0 = make_float2(acc[mf][nf][0], acc[mf][nf][1]);
                float2 v1 = make_float2(acc[mf][nf][2], acc[mf][nf][3]);
                *(float2*)(yp + (size_t)row0 * D + col)       = v0;
                *(float2*)(yp + (size_t)(row0 + 8) * D + col) = v1;
            }
        }
        __syncthreads();   // protect buf from next iteration's prefetch
        if (DB) buf ^= 1;

        if (!DB && tile + GRID < TILES)
            load_x_tile(X + (size_t)(tile + GRID) * BM * D, sx, tid);
    }
}

// ---------------------------------------------------------------------------
extern "C" void kernel_launch(void* const* d_in, const int* in_sizes, int n_in,
                              void* d_out, int out_size) {
    const float* X = (const float*)d_in[0];  // [524288, 128]
    const float* W = (const float*)d_in[1];  // [16, 128, 128]
    const float* s = (const float*)d_in[2];  // [16, 1]
    float* Y = (float*)d_out;                // [524288, 128]

    prep_kernel<<<32, 256>>>(W, s);

    size_t smem_db = (16384 + 2 * BM * XSTRIDE) * sizeof(float);  // ~196 KB
    size_t smem_sb = (16384 + 1 * BM * XSTRIDE) * sizeof(float);  // ~132 KB

    cudaError_t e = cudaFuncSetAttribute(
        gemm_kernel<1>, cudaFuncAttributeMaxDynamicSharedMemorySize, (int)smem_db);
    if (e == cudaSuccess) {
        gemm_kernel<1><<<GRID, 256, smem_db>>>(X, Y);
    } else {
        cudaGetLastError();  // clear sticky error
        cudaFuncSetAttribute(gemm_kernel<0>,
                             cudaFuncAttributeMaxDynamicSharedMemorySize, (int)smem_sb);
        gemm_kernel<0><<<GRID, 256, smem_sb>>>(X, Y);
    }
}